// round 13
// baseline (speedup 1.0000x reference)
#include <cuda_runtime.h>
#include <cuda_fp16.h>
#include <math.h>
#include <cstdint>

// ---------------------------------------------------------------------------
// CLIP ViT-B/16 visual tower on GB300 — 1-term fp16 mma.sync GEMMs (occ=2)
// + split-CTA tensor-core attention (1 q-tile per warp) + fast LN.
// ---------------------------------------------------------------------------

#define Bsz 32
#define Dm  768
#define Hh  12
#define HD  64
#define Ff  3072
#define Ll  12
#define Ss  197
#define Oo  512
#define NPATCH 196
#define NTOK (Bsz * Ss)        // 6304
#define NPROW (Bsz * NPATCH)   // 6272

// ------------------------- helpers -----------------------------------------
__device__ __forceinline__ uint32_t smem_u32(const void* p) {
    uint32_t a;
    asm("{ .reg .u64 t; cvta.to.shared.u64 t, %1; cvt.u32.u64 %0, t; }"
        : "=r"(a) : "l"(p));
    return a;
}
__device__ __forceinline__ void cpa16(uint32_t dst, const void* src, uint32_t vsz) {
    asm volatile("cp.async.cg.shared.global [%0], [%1], 16, %2;"
                 :: "r"(dst), "l"(src), "r"(vsz) : "memory");
}
#define CP_COMMIT() asm volatile("cp.async.commit_group;" ::: "memory")
#define CP_WAIT0()  asm volatile("cp.async.wait_group 0;" ::: "memory")
#define CP_WAIT1()  asm volatile("cp.async.wait_group 1;" ::: "memory")

#define MMA16816(c, a0, a1, a2, a3, b0, b1) \
    asm volatile("mma.sync.aligned.m16n8k16.row.col.f32.f16.f16.f32 " \
        "{%0,%1,%2,%3}, {%4,%5,%6,%7}, {%8,%9}, {%0,%1,%2,%3};" \
        : "+f"((c)[0]), "+f"((c)[1]), "+f"((c)[2]), "+f"((c)[3]) \
        : "r"(a0), "r"(a1), "r"(a2), "r"(a3), "r"(b0), "r"(b1))

#define LDSM4(r0, r1, r2, r3, addr) \
    asm volatile("ldmatrix.sync.aligned.m8n8.x4.shared.b16 {%0,%1,%2,%3}, [%4];" \
        : "=r"(r0), "=r"(r1), "=r"(r2), "=r"(r3) : "r"(addr))

// ------------------------- scratch (static device globals) -----------------
#define OFF_CONV 0ul
#define OFF_QKV  589824ul
#define OFF_OUT  21823488ul
#define OFF_FC   28901376ul
#define OFF_PROJ 57212928ul
#define WTOT     85524480ul

__device__ __align__(16) __half g_w[WTOT];         // fp16 weights
__device__ __align__(16) __half g_xp[NPROW * Dm];  // fp16 patch matrix
__device__ __align__(16) float g_pe[NPROW * Dm];
__device__ __align__(16) float g_x [NTOK * Dm];    // fp32 residual stream
__device__ __align__(16) __half g_h[NTOK * Dm];    // fp16 LN output
__device__ __align__(16) __half g_qkvh[NTOK * 3 * Dm]; // fp16 qkv
__device__ __align__(16) __half g_ao[NTOK * Dm];   // fp16 attn out
__device__ __align__(16) __half g_mlp[NTOK * Ff];  // fp16 mlp hidden
__device__ __align__(16) float g_cls[Bsz * Dm];

// --------------- all weights fp32 -> fp16, one kernel ----------------------
#define F4_CONV (589824 / 4)
#define F4_QKV  (21233664 / 4)
#define F4_OUT  (7077888 / 4)
#define F4_FC   (28311552 / 4)
#define F4_PROJ (28311552 / 4)
#define F4_TOT  (F4_CONV + F4_QKV + F4_OUT + F4_FC + F4_PROJ)

__global__ __launch_bounds__(256) void k_cvt_all(
    const float4* __restrict__ s_conv, const float4* __restrict__ s_qkv,
    const float4* __restrict__ s_out,  const float4* __restrict__ s_fc,
    const float4* __restrict__ s_proj, __half2* __restrict__ w)
{
    long i = (long)blockIdx.x * blockDim.x + threadIdx.x;
    if (i >= F4_TOT) return;
    const float4* src;
    long loc; unsigned long dst;
    if (i < F4_CONV) { src = s_conv; loc = i; dst = OFF_CONV / 2 + loc * 2; }
    else if (i < F4_CONV + F4_QKV) { src = s_qkv; loc = i - F4_CONV; dst = OFF_QKV / 2 + loc * 2; }
    else if (i < F4_CONV + F4_QKV + F4_OUT) { src = s_out; loc = i - F4_CONV - F4_QKV; dst = OFF_OUT / 2 + loc * 2; }
    else if (i < F4_CONV + F4_QKV + F4_OUT + F4_FC) { src = s_fc; loc = i - F4_CONV - F4_QKV - F4_OUT; dst = OFF_FC / 2 + loc * 2; }
    else { src = s_proj; loc = i - F4_CONV - F4_QKV - F4_OUT - F4_FC; dst = OFF_PROJ / 2 + loc * 2; }
    float4 v = src[loc];
    w[dst]     = __floats2half2_rn(v.x, v.y);
    w[dst + 1] = __floats2half2_rn(v.z, v.w);
}

// ------------------------- patchify + normalize -> fp16 --------------------
__global__ void k_patchify(const float* __restrict__ img, __half* __restrict__ xh)
{
    const float mean[3] = {0.48145466f, 0.4578275f, 0.40821073f};
    const float istd[3] = {1.f/0.26862954f, 1.f/0.26130258f, 1.f/0.27577711f};
    int idx = blockIdx.x * blockDim.x + threadIdx.x;
    if (idx >= NPROW * Dm) return;
    int col = idx % Dm;
    int row = idx / Dm;
    int b  = row / NPATCH;
    int p  = row % NPATCH;
    int py = p / 14, px = p % 14;
    int c  = col >> 8;
    int rem = col & 255;
    int ph = rem >> 4, pw = rem & 15;
    float v = img[(((size_t)b * 3 + c) * 224 + py * 16 + ph) * 224 + px * 16 + pw];
    xh[idx] = __float2half((v - mean[c]) * istd[c]);
}

// ------------------------- mma.sync fp16 GEMM (occ=2) ----------------------
#define STG_MAT   18432            // 128 rows * 144 B
#define STG_BYTES 36864            // 2 matrices (A, B)
#define MM_SMEM   (3 * STG_BYTES)  // 110592

template<bool BIAS, bool RES, bool GELU_, bool F16O>
__global__ __launch_bounds__(256, 2) void k_mm(
    const __half* __restrict__ A, const __half* __restrict__ B,
    const float* __restrict__ bias, const float* __restrict__ resi,
    float* __restrict__ C, __half* __restrict__ Ch,
    int M, int N, int K)
{
    extern __shared__ char smc[];
    const uint32_t sb = smem_u32(smc);
    const int tid = threadIdx.x, lane = tid & 31, wid = tid >> 5;
    const int warp_m = wid & 3, warp_n = wid >> 2;
    const int bm = blockIdx.y * 128, bn = blockIdx.x * 128;
    const int Kd8 = K >> 3, nch = K >> 6;

    const uint4* A4 = (const uint4*)A;
    const uint4* B4 = (const uint4*)B;

    float acc[2][8][4];
    #pragma unroll
    for (int a = 0; a < 2; a++)
        #pragma unroll
        for (int b = 0; b < 8; b++)
            #pragma unroll
            for (int c = 0; c < 4; c++) acc[a][b][c] = 0.f;

    auto load_chunk = [&](int i, int s) {
        int k0d8 = i << 3;
        uint32_t stg = sb + s * STG_BYTES;
        #pragma unroll
        for (int t = tid; t < 2048; t += 256) {
            int mat = t >> 10, r = (t >> 3) & 127, c8 = t & 7;
            uint32_t dst = stg + mat * STG_MAT + r * 144 + c8 * 16;
            if (mat == 0) {
                int grow = bm + r;
                int ok = grow < M;
                const uint4* src = A4 + (size_t)(ok ? grow : 0) * Kd8 + k0d8 + c8;
                cpa16(dst, src, ok ? 16u : 0u);
            } else {
                const uint4* src = B4 + (size_t)(bn + r) * Kd8 + k0d8 + c8;
                cpa16(dst, src, 16u);
            }
        }
        CP_COMMIT();
    };

    load_chunk(0, 0);
    load_chunk(1, 1);

    const uint32_t aoff = (uint32_t)((warp_m * 32 + (lane & 15)) * 144 + ((lane >> 4) << 4));
    const int brow = (lane & 7) + ((lane >> 4) << 3);
    const uint32_t boff = (uint32_t)(STG_MAT + (warp_n * 64 + brow) * 144
                                     + (((lane >> 3) & 1) << 4));

    int s = 0;
    for (int i = 0; i < nch; i++) {
        if (i + 1 < nch) CP_WAIT1(); else CP_WAIT0();
        __syncthreads();
        if (i + 2 < nch) {
            int s2 = s + 2; if (s2 >= 3) s2 -= 3;
            load_chunk(i + 2, s2);
        }
        uint32_t stg = sb + s * STG_BYTES;
        uint32_t aA = stg + aoff, bB = stg + boff;
        #pragma unroll
        for (int k16 = 0; k16 < 4; k16++) {
            uint32_t ah[2][4], bf[4][4];
            #pragma unroll
            for (int mf = 0; mf < 2; mf++)
                LDSM4(ah[mf][0], ah[mf][1], ah[mf][2], ah[mf][3],
                      aA + mf * (16 * 144) + k16 * 32);
            #pragma unroll
            for (int p = 0; p < 4; p++)
                LDSM4(bf[p][0], bf[p][1], bf[p][2], bf[p][3],
                      bB + p * (16 * 144) + k16 * 32);
            #pragma unroll
            for (int p = 0; p < 4; p++)
                #pragma unroll
                for (int sub = 0; sub < 2; sub++)
                    #pragma unroll
                    for (int mf = 0; mf < 2; mf++)
                        MMA16816(acc[mf][p * 2 + sub],
                                 ah[mf][0], ah[mf][1], ah[mf][2], ah[mf][3],
                                 bf[p][2 * sub], bf[p][2 * sub + 1]);
        }
        s++; if (s == 3) s = 0;
    }

    // ---- epilogue (paired stores) ----
    const int qrow = lane >> 2;
    #pragma unroll
    for (int mf = 0; mf < 2; mf++) {
        #pragma unroll
        for (int nf = 0; nf < 8; nf++) {
            int col = bn + warp_n * 64 + nf * 8 + ((lane & 3) << 1);
            float b0 = 0.f, b1 = 0.f;
            if (BIAS) { b0 = bias[col]; b1 = bias[col + 1]; }
            #pragma unroll
            for (int er = 0; er < 2; er++) {
                int row = bm + warp_m * 32 + mf * 16 + qrow + er * 8;
                if (row >= M) continue;
                float v0 = acc[mf][nf][er * 2 + 0] + b0;
                float v1 = acc[mf][nf][er * 2 + 1] + b1;
                if (GELU_) {
                    v0 = v0 / (1.f + __expf(-1.702f * v0));
                    v1 = v1 / (1.f + __expf(-1.702f * v1));
                }
                if (RES) {
                    float2 rr = *(const float2*)(resi + (size_t)row * N + col);
                    v0 += rr.x; v1 += rr.y;
                }
                if (F16O) {
                    *(__half2*)(Ch + (size_t)row * N + col) = __floats2half2_rn(v0, v1);
                } else {
                    float2 o; o.x = v0; o.y = v1;
                    *(float2*)(C + (size_t)row * N + col) = o;
                }
            }
        }
    }
}

// ------------------------- split-CTA tensor-core attention -----------------
// 2 CTAs per (b, head); each CTA: 8 warps, ONE q-tile per warp (balanced).
#define ATT_SMEM 87552  // Q 208x72 + K 208x72 + Vt 64x216 halves

__global__ __launch_bounds__(256) void k_attn(const __half* __restrict__ QKV,
                                              __half* __restrict__ out)
{
    extern __shared__ __half sm[];
    __half* Qs = sm;             // 208 rows x 72 halves (144 B stride)
    __half* Ks = sm + 14976;     // 208 x 72
    __half* Vt = sm + 29952;     // 64 x 216 halves (432 B stride)
    const int bh = blockIdx.x >> 1, half = blockIdx.x & 1;
    const int b = bh / Hh, h = bh % Hh;
    const int tid = threadIdx.x, lane = tid & 31, wid = tid >> 5;

    for (int i = tid; i < 64 * 19; i += 256) {
        int d = i / 19, s_ = 197 + i % 19;
        Vt[d * 216 + s_] = __ushort_as_half(0);
    }

    const __half* qp = QKV + (size_t)b * Ss * (3 * Dm) + h * HD;
    const __half2 qscale = __float2half2_rn(0.125f);
    // K, V: full; Q: only this half's rows [half*112, half*112+112) ∩ [0,197)
    for (int idx = tid; idx < Ss * 8; idx += 256) {
        int s_ = idx >> 3, c8 = idx & 7;
        const uint4* row = (const uint4*)(qp + (size_t)s_ * (3 * Dm));
        uint4 kv = row[Dm / 8 + c8];
        uint4 vv = row[2 * Dm / 8 + c8];
        *(uint4*)(Ks + s_ * 72 + c8 * 8) = kv;
        __half* hv = (__half*)&vv;
        #pragma unroll
        for (int j = 0; j < 8; j++) Vt[(c8 * 8 + j) * 216 + s_] = hv[j];
        int qlo = half * 112;
        if (s_ >= qlo && s_ < qlo + 112) {
            uint4 qv = row[c8];
            __half2* q2 = (__half2*)&qv;
            #pragma unroll
            for (int j = 0; j < 4; j++) q2[j] = __hmul2(q2[j], qscale);
            *(uint4*)(Qs + s_ * 72 + c8 * 8) = qv;
        }
    }
    __syncthreads();

    const uint32_t qsb = smem_u32(Qs), ksb = smem_u32(Ks), vtb = smem_u32(Vt);
    const uint32_t arow = (uint32_t)((lane & 15) * 144 + ((lane >> 4) << 4));
    const uint32_t brow = (uint32_t)(((lane & 7) + ((lane >> 4) << 3)) * 144
                                     + (((lane >> 3) & 1) << 4));
    const uint32_t vrow = (uint32_t)(((lane & 7) + ((lane >> 4) << 3)) * 432
                                     + (((lane >> 3) & 1) << 4));
    const int r = lane >> 2, cq = (lane & 3) << 1;

    int qt = half * 7 + wid;            // half 0: 0..7? no: 0..6 ; half 1: 7..13
    if (half == 0 ? (qt > 6) : (qt > 12)) return;   // 7 warps in half0... see grid note
    {
        float sacc[26][4];
        #pragma unroll
        for (int f = 0; f < 26; f++)
            #pragma unroll
            for (int e = 0; e < 4; e++) sacc[f][e] = 0.f;
        #pragma unroll
        for (int k16 = 0; k16 < 4; k16++) {
            uint32_t aq0, aq1, aq2, aq3;
            LDSM4(aq0, aq1, aq2, aq3, qsb + qt * (16 * 144) + arow + k16 * 32);
            #pragma unroll
            for (int p = 0; p < 13; p++) {
                uint32_t kb[4];
                LDSM4(kb[0], kb[1], kb[2], kb[3], ksb + p * (16 * 144) + brow + k16 * 32);
                MMA16816(sacc[2 * p],     aq0, aq1, aq2, aq3, kb[0], kb[1]);
                MMA16816(sacc[2 * p + 1], aq0, aq1, aq2, aq3, kb[2], kb[3]);
            }
        }
        #pragma unroll
        for (int f = 0; f < 26; f++) {
            int c0 = 8 * f + cq;
            if (c0 >= Ss)     { sacc[f][0] = -1e30f; sacc[f][2] = -1e30f; }
            if (c0 + 1 >= Ss) { sacc[f][1] = -1e30f; sacc[f][3] = -1e30f; }
        }
        float mx0 = -1e30f, mx1 = -1e30f;
        #pragma unroll
        for (int f = 0; f < 26; f++) {
            mx0 = fmaxf(mx0, fmaxf(sacc[f][0], sacc[f][1]));
            mx1 = fmaxf(mx1, fmaxf(sacc[f][2], sacc[f][3]));
        }
        mx0 = fmaxf(mx0, __shfl_xor_sync(~0u, mx0, 1));
        mx0 = fmaxf(mx0, __shfl_xor_sync(~0u, mx0, 2));
        mx1 = fmaxf(mx1, __shfl_xor_sync(~0u, mx1, 1));
        mx1 = fmaxf(mx1, __shfl_xor_sync(~0u, mx1, 2));
        float sum0 = 0.f, sum1 = 0.f;
        #pragma unroll
        for (int f = 0; f < 26; f++) {
            sacc[f][0] = __expf(sacc[f][0] - mx0);
            sacc[f][1] = __expf(sacc[f][1] - mx0);
            sacc[f][2] = __expf(sacc[f][2] - mx1);
            sacc[f][3] = __expf(sacc[f][3] - mx1);
            sum0 += sacc[f][0] + sacc[f][1];
            sum1 += sacc[f][2] + sacc[f][3];
        }
        sum0 += __shfl_xor_sync(~0u, sum0, 1);
        sum0 += __shfl_xor_sync(~0u, sum0, 2);
        sum1 += __shfl_xor_sync(~0u, sum1, 1);
        sum1 += __shfl_xor_sync(~0u, sum1, 2);
        float inv0 = 1.f / sum0, inv1 = 1.f / sum1;
        uint32_t pa[13][4];
        #pragma unroll
        for (int kk = 0; kk < 13; kk++) {
            __half2 t0 = __floats2half2_rn(sacc[2*kk][0] * inv0,   sacc[2*kk][1] * inv0);
            __half2 t1 = __floats2half2_rn(sacc[2*kk][2] * inv1,   sacc[2*kk][3] * inv1);
            __half2 t2 = __floats2half2_rn(sacc[2*kk+1][0] * inv0, sacc[2*kk+1][1] * inv0);
            __half2 t3 = __floats2half2_rn(sacc[2*kk+1][2] * inv1, sacc[2*kk+1][3] * inv1);
            pa[kk][0] = *(uint32_t*)&t0;
            pa[kk][1] = *(uint32_t*)&t1;
            pa[kk][2] = *(uint32_t*)&t2;
            pa[kk][3] = *(uint32_t*)&t3;
        }
        float oacc[8][4];
        #pragma unroll
        for (int f = 0; f < 8; f++)
            #pragma unroll
            for (int e = 0; e < 4; e++) oacc[f][e] = 0.f;
        #pragma unroll
        for (int kk = 0; kk < 13; kk++) {
            #pragma unroll
            for (int pv = 0; pv < 4; pv++) {
                uint32_t vb[4];
                LDSM4(vb[0], vb[1], vb[2], vb[3], vtb + pv * (16 * 432) + vrow + kk * 32);
                MMA16816(oacc[2 * pv],     pa[kk][0], pa[kk][1], pa[kk][2], pa[kk][3],
                         vb[0], vb[1]);
                MMA16816(oacc[2 * pv + 1], pa[kk][0], pa[kk][1], pa[kk][2], pa[kk][3],
                         vb[2], vb[3]);
            }
        }
        #pragma unroll
        for (int f = 0; f < 8; f++) {
            int d = 8 * f + cq;
            #pragma unroll
            for (int er = 0; er < 2; er++) {
                int q = qt * 16 + r + er * 8;
                if (q < Ss)
                    *(__half2*)(out + ((size_t)(b * Ss + q)) * Dm + h * HD + d)
                        = __floats2half2_rn(oacc[f][er * 2], oacc[f][er * 2 + 1]);
            }
        }
    }
}

// ------------------------- warp-per-row LayerNorm --------------------------
template<bool F16>
__global__ __launch_bounds__(256) void k_ln(
    const float* __restrict__ in, float* __restrict__ outf, __half* __restrict__ oh,
    const float* __restrict__ sc, const float* __restrict__ bi,
    long in_stride, long out_stride, int nrows)
{
    int row = blockIdx.x * 8 + (threadIdx.x >> 5);
    if (row >= nrows) return;
    int lane = threadIdx.x & 31;
    const float4* ip = (const float4*)(in + (size_t)row * in_stride);
    float4 v[6];
    float s = 0.f, sq = 0.f;
    #pragma unroll
    for (int j = 0; j < 6; j++) {
        v[j] = ip[j * 32 + lane];
        s  += v[j].x + v[j].y + v[j].z + v[j].w;
        sq += v[j].x*v[j].x + v[j].y*v[j].y + v[j].z*v[j].z + v[j].w*v[j].w;
    }
    #pragma unroll
    for (int o = 16; o > 0; o >>= 1) {
        s  += __shfl_xor_sync(~0u, s, o);
        sq += __shfl_xor_sync(~0u, sq, o);
    }
    float mean = s * (1.f / Dm);
    float var  = sq * (1.f / Dm) - mean * mean;
    float r = rsqrtf(var + 1e-5f);
    const float4* sc4 = (const float4*)sc;
    const float4* bi4 = (const float4*)bi;
    #pragma unroll
    for (int j = 0; j < 6; j++) {
        float4 g = sc4[j * 32 + lane], be = bi4[j * 32 + lane];
        float y0 = (v[j].x - mean) * r * g.x + be.x;
        float y1 = (v[j].y - mean) * r * g.y + be.y;
        float y2 = (v[j].z - mean) * r * g.z + be.z;
        float y3 = (v[j].w - mean) * r * g.w + be.w;
        if (F16) {
            __half2 h0 = __floats2half2_rn(y0, y1);
            __half2 h1 = __floats2half2_rn(y2, y3);
            uint2 pk; pk.x = *(uint32_t*)&h0; pk.y = *(uint32_t*)&h1;
            ((uint2*)(oh + (size_t)row * out_stride))[j * 32 + lane] = pk;
        } else {
            float4 o; o.x = y0; o.y = y1; o.z = y2; o.w = y3;
            ((float4*)(outf + (size_t)row * out_stride))[j * 32 + lane] = o;
        }
    }
}

// --------------- fused assemble (cls+patch+pos) + ln_pre -> x --------------
__global__ __launch_bounds__(256) void k_asmln(
    const float* __restrict__ pe, const float* __restrict__ cls,
    const float* __restrict__ pos,
    const float* __restrict__ sc, const float* __restrict__ bi,
    float* __restrict__ x)
{
    int t = blockIdx.x * 8 + (threadIdx.x >> 5);
    if (t >= NTOK) return;
    int lane = threadIdx.x & 31;
    int s_ = t % Ss, b = t / Ss;
    const float4* src4 = (s_ == 0) ? (const float4*)cls
                       : (const float4*)(pe + (size_t)(b * NPATCH + s_ - 1) * Dm);
    const float4* pos4 = (const float4*)(pos + (size_t)s_ * Dm);
    float4 v[6];
    float s = 0.f, sq = 0.f;
    #pragma unroll
    for (int j = 0; j < 6; j++) {
        float4 a = src4[j * 32 + lane], p = pos4[j * 32 + lane];
        v[j].x = a.x + p.x; v[j].y = a.y + p.y; v[j].z = a.z + p.z; v[j].w = a.w + p.w;
        s  += v[j].x + v[j].y + v[j].z + v[j].w;
        sq += v[j].x*v[j].x + v[j].y*v[j].y + v[j].z*v[j].z + v[j].w*v[j].w;
    }
    #pragma unroll
    for (int o = 16; o > 0; o >>= 1) {
        s  += __shfl_xor_sync(~0u, s, o);
        sq += __shfl_xor_sync(~0u, sq, o);
    }
    float mean = s * (1.f / Dm);
    float var  = sq * (1.f / Dm) - mean * mean;
    float r = rsqrtf(var + 1e-5f);
    const float4* sc4 = (const float4*)sc;
    const float4* bi4 = (const float4*)bi;
    #pragma unroll
    for (int j = 0; j < 6; j++) {
        float4 g = sc4[j * 32 + lane], be = bi4[j * 32 + lane];
        float4 o;
        o.x = (v[j].x - mean) * r * g.x + be.x;
        o.y = (v[j].y - mean) * r * g.y + be.y;
        o.z = (v[j].z - mean) * r * g.z + be.z;
        o.w = (v[j].w - mean) * r * g.w + be.w;
        ((float4*)(x + (size_t)t * Dm))[j * 32 + lane] = o;
    }
}

// ------------------------- head: cls_ln @ vis_proj -------------------------
__global__ __launch_bounds__(512) void k_head(const float* __restrict__ cls,
                                              const float* __restrict__ Wp,
                                              float* __restrict__ out)
{
    __shared__ float row[Dm];
    int b = blockIdx.x;
    for (int i = threadIdx.x; i < Dm; i += 512) row[i] = cls[(size_t)b * Dm + i];
    __syncthreads();
    int o = threadIdx.x;
    float acc = 0.f;
    for (int d = 0; d < Dm; d++) acc += row[d] * Wp[(size_t)d * Oo + o];
    out[(size_t)b * Oo + o] = acc;
}

// ---------------------------------------------------------------------------
extern "C" void kernel_launch(void* const* d_in, const int* in_sizes, int n_in,
                              void* d_out, int out_size)
{
    const float* images   = (const float*)d_in[0];
    const float* conv_w   = (const float*)d_in[1];
    const float* cls_emb  = (const float*)d_in[2];
    const float* pos_emb  = (const float*)d_in[3];
    const float* ln_pre_s = (const float*)d_in[4];
    const float* ln_pre_b = (const float*)d_in[5];
    const float* ln1_s    = (const float*)d_in[6];
    const float* ln1_b    = (const float*)d_in[7];
    const float* qkv_w    = (const float*)d_in[8];
    const float* qkv_b    = (const float*)d_in[9];
    const float* out_w    = (const float*)d_in[10];
    const float* out_b    = (const float*)d_in[11];
    const float* ln2_s    = (const float*)d_in[12];
    const float* ln2_b    = (const float*)d_in[13];
    const float* fc_w     = (const float*)d_in[14];
    const float* fc_b     = (const float*)d_in[15];
    const float* proj_w   = (const float*)d_in[16];
    const float* proj_b   = (const float*)d_in[17];
    const float* lnp_s    = (const float*)d_in[18];
    const float* lnp_b    = (const float*)d_in[19];
    const float* vis_proj = (const float*)d_in[20];
    float* outp = (float*)d_out;

    __half *w, *xp, *h, *qkvh, *ao, *mlp;
    float *pe, *x, *cls;
    cudaGetSymbolAddress((void**)&w,    g_w);
    cudaGetSymbolAddress((void**)&xp,   g_xp);
    cudaGetSymbolAddress((void**)&pe,   g_pe);
    cudaGetSymbolAddress((void**)&x,    g_x);
    cudaGetSymbolAddress((void**)&h,    g_h);
    cudaGetSymbolAddress((void**)&qkvh, g_qkvh);
    cudaGetSymbolAddress((void**)&ao,   g_ao);
    cudaGetSymbolAddress((void**)&mlp,  g_mlp);
    cudaGetSymbolAddress((void**)&cls,  g_cls);

    cudaFuncSetAttribute(k_mm<false,false,false,false>, cudaFuncAttributeMaxDynamicSharedMemorySize, MM_SMEM);
    cudaFuncSetAttribute(k_mm<true, false,false,true >, cudaFuncAttributeMaxDynamicSharedMemorySize, MM_SMEM);
    cudaFuncSetAttribute(k_mm<true, true, false,false>, cudaFuncAttributeMaxDynamicSharedMemorySize, MM_SMEM);
    cudaFuncSetAttribute(k_mm<true, false,true, true >, cudaFuncAttributeMaxDynamicSharedMemorySize, MM_SMEM);
    cudaFuncSetAttribute(k_attn, cudaFuncAttributeMaxDynamicSharedMemorySize, ATT_SMEM);

    // ---- all weights fp32 -> fp16, one launch ----
    k_cvt_all<<<(F4_TOT + 255) / 256, 256>>>(
        (const float4*)conv_w, (const float4*)qkv_w, (const float4*)out_w,
        (const float4*)fc_w, (const float4*)proj_w, (__half2*)w);

    // ---- stem ----
    k_patchify<<<(NPROW * Dm + 255) / 256, 256>>>(images, xp);
    k_mm<false,false,false,false><<<dim3(Dm / 128, (NPROW + 127) / 128), 256, MM_SMEM>>>(
        xp, w + OFF_CONV, nullptr, nullptr, pe, nullptr, NPROW, Dm, Dm);
    k_asmln<<<(NTOK + 7) / 8, 256>>>(pe, cls_emb, pos_emb, ln_pre_s, ln_pre_b, x);

    // ---- transformer layers ----
    for (int l = 0; l < Ll; l++) {
        const float* l1s = ln1_s + (size_t)l * Dm;
        const float* l1b = ln1_b + (size_t)l * Dm;
        const float* qb  = qkv_b + (size_t)l * 3 * Dm;
        const float* ob  = out_b + (size_t)l * Dm;
        const float* l2s = ln2_s + (size_t)l * Dm;
        const float* l2b = ln2_b + (size_t)l * Dm;
        const float* fb  = fc_b  + (size_t)l * Ff;
        const float* pb  = proj_b + (size_t)l * Dm;
        const __half* qw = w + OFF_QKV  + (size_t)l * 2304 * 768;
        const __half* ow = w + OFF_OUT  + (size_t)l * 768 * 768;
        const __half* fw = w + OFF_FC   + (size_t)l * 3072 * 768;
        const __half* pw = w + OFF_PROJ + (size_t)l * 768 * 3072;

        k_ln<true><<<(NTOK + 7) / 8, 256>>>(x, nullptr, h, l1s, l1b, Dm, Dm, NTOK);
        k_mm<true,false,false,true><<<dim3(3 * Dm / 128, (NTOK + 127) / 128), 256, MM_SMEM>>>(
            h, qw, qb, nullptr, nullptr, qkvh, NTOK, 3 * Dm, Dm);
        k_attn<<<Bsz * Hh * 2, 256, ATT_SMEM>>>(qkvh, ao);
        k_mm<true,true,false,false><<<dim3(Dm / 128, (NTOK + 127) / 128), 256, MM_SMEM>>>(
            ao, ow, ob, x, x, nullptr, NTOK, Dm, Dm);
        k_ln<true><<<(NTOK + 7) / 8, 256>>>(x, nullptr, h, l2s, l2b, Dm, Dm, NTOK);
        k_mm<true,false,true,true><<<dim3(Ff / 128, (NTOK + 127) / 128), 256, MM_SMEM>>>(
            h, fw, fb, nullptr, nullptr, mlp, NTOK, Ff, Dm);
        k_mm<true,true,false,false><<<dim3(Dm / 128, (NTOK + 127) / 128), 256, MM_SMEM>>>(
            mlp, pw, pb, x, x, nullptr, NTOK, Dm, Ff);
    }

    // ---- head ----
    k_ln<false><<<4, 256>>>(x, cls, nullptr, lnp_s, lnp_b, (long)Ss * Dm, Dm, Bsz);
    k_head<<<Bsz, 512>>>(cls, vis_proj, outp);
}

// round 14
// speedup vs baseline: 1.0381x; 1.0381x over previous
#include <cuda_runtime.h>
#include <cuda_fp16.h>
#include <math.h>
#include <cstdint>

// ---------------------------------------------------------------------------
// CLIP ViT-B/16 visual tower on GB300 — 1-term fp16 mma.sync GEMMs (occ=2)
// + 13-warp tensor-core attention (one q-tile per warp) + fast LN.
// ---------------------------------------------------------------------------

#define Bsz 32
#define Dm  768
#define Hh  12
#define HD  64
#define Ff  3072
#define Ll  12
#define Ss  197
#define Oo  512
#define NPATCH 196
#define NTOK (Bsz * Ss)        // 6304
#define NPROW (Bsz * NPATCH)   // 6272

// ------------------------- helpers -----------------------------------------
__device__ __forceinline__ uint32_t smem_u32(const void* p) {
    uint32_t a;
    asm("{ .reg .u64 t; cvta.to.shared.u64 t, %1; cvt.u32.u64 %0, t; }"
        : "=r"(a) : "l"(p));
    return a;
}
__device__ __forceinline__ void cpa16(uint32_t dst, const void* src, uint32_t vsz) {
    asm volatile("cp.async.cg.shared.global [%0], [%1], 16, %2;"
                 :: "r"(dst), "l"(src), "r"(vsz) : "memory");
}
#define CP_COMMIT() asm volatile("cp.async.commit_group;" ::: "memory")
#define CP_WAIT0()  asm volatile("cp.async.wait_group 0;" ::: "memory")
#define CP_WAIT1()  asm volatile("cp.async.wait_group 1;" ::: "memory")

#define MMA16816(c, a0, a1, a2, a3, b0, b1) \
    asm volatile("mma.sync.aligned.m16n8k16.row.col.f32.f16.f16.f32 " \
        "{%0,%1,%2,%3}, {%4,%5,%6,%7}, {%8,%9}, {%0,%1,%2,%3};" \
        : "+f"((c)[0]), "+f"((c)[1]), "+f"((c)[2]), "+f"((c)[3]) \
        : "r"(a0), "r"(a1), "r"(a2), "r"(a3), "r"(b0), "r"(b1))

#define LDSM4(r0, r1, r2, r3, addr) \
    asm volatile("ldmatrix.sync.aligned.m8n8.x4.shared.b16 {%0,%1,%2,%3}, [%4];" \
        : "=r"(r0), "=r"(r1), "=r"(r2), "=r"(r3) : "r"(addr))

// ------------------------- scratch (static device globals) -----------------
#define OFF_CONV 0ul
#define OFF_QKV  589824ul
#define OFF_OUT  21823488ul
#define OFF_FC   28901376ul
#define OFF_PROJ 57212928ul
#define WTOT     85524480ul

__device__ __align__(16) __half g_w[WTOT];         // fp16 weights
__device__ __align__(16) __half g_xp[NPROW * Dm];  // fp16 patch matrix
__device__ __align__(16) float g_pe[NPROW * Dm];
__device__ __align__(16) float g_x [NTOK * Dm];    // fp32 residual stream
__device__ __align__(16) __half g_h[NTOK * Dm];    // fp16 LN output
__device__ __align__(16) __half g_qkvh[NTOK * 3 * Dm]; // fp16 qkv
__device__ __align__(16) __half g_ao[NTOK * Dm];   // fp16 attn out
__device__ __align__(16) __half g_mlp[NTOK * Ff];  // fp16 mlp hidden
__device__ __align__(16) float g_cls[Bsz * Dm];

// --------------- all weights fp32 -> fp16, one kernel ----------------------
#define F4_CONV (589824 / 4)
#define F4_QKV  (21233664 / 4)
#define F4_OUT  (7077888 / 4)
#define F4_FC   (28311552 / 4)
#define F4_PROJ (28311552 / 4)
#define F4_TOT  (F4_CONV + F4_QKV + F4_OUT + F4_FC + F4_PROJ)

__global__ __launch_bounds__(256) void k_cvt_all(
    const float4* __restrict__ s_conv, const float4* __restrict__ s_qkv,
    const float4* __restrict__ s_out,  const float4* __restrict__ s_fc,
    const float4* __restrict__ s_proj, __half2* __restrict__ w)
{
    long i = (long)blockIdx.x * blockDim.x + threadIdx.x;
    if (i >= F4_TOT) return;
    const float4* src;
    long loc; unsigned long dst;
    if (i < F4_CONV) { src = s_conv; loc = i; dst = OFF_CONV / 2 + loc * 2; }
    else if (i < F4_CONV + F4_QKV) { src = s_qkv; loc = i - F4_CONV; dst = OFF_QKV / 2 + loc * 2; }
    else if (i < F4_CONV + F4_QKV + F4_OUT) { src = s_out; loc = i - F4_CONV - F4_QKV; dst = OFF_OUT / 2 + loc * 2; }
    else if (i < F4_CONV + F4_QKV + F4_OUT + F4_FC) { src = s_fc; loc = i - F4_CONV - F4_QKV - F4_OUT; dst = OFF_FC / 2 + loc * 2; }
    else { src = s_proj; loc = i - F4_CONV - F4_QKV - F4_OUT - F4_FC; dst = OFF_PROJ / 2 + loc * 2; }
    float4 v = src[loc];
    w[dst]     = __floats2half2_rn(v.x, v.y);
    w[dst + 1] = __floats2half2_rn(v.z, v.w);
}

// ------------------------- patchify + normalize -> fp16 --------------------
__global__ void k_patchify(const float* __restrict__ img, __half* __restrict__ xh)
{
    const float mean[3] = {0.48145466f, 0.4578275f, 0.40821073f};
    const float istd[3] = {1.f/0.26862954f, 1.f/0.26130258f, 1.f/0.27577711f};
    int idx = blockIdx.x * blockDim.x + threadIdx.x;
    if (idx >= NPROW * Dm) return;
    int col = idx % Dm;
    int row = idx / Dm;
    int b  = row / NPATCH;
    int p  = row % NPATCH;
    int py = p / 14, px = p % 14;
    int c  = col >> 8;
    int rem = col & 255;
    int ph = rem >> 4, pw = rem & 15;
    float v = img[(((size_t)b * 3 + c) * 224 + py * 16 + ph) * 224 + px * 16 + pw];
    xh[idx] = __float2half((v - mean[c]) * istd[c]);
}

// ------------------------- mma.sync fp16 GEMM (occ=2) ----------------------
#define STG_MAT   18432            // 128 rows * 144 B
#define STG_BYTES 36864            // 2 matrices (A, B)
#define MM_SMEM   (3 * STG_BYTES)  // 110592

template<bool BIAS, bool RES, bool GELU_, bool F16O>
__global__ __launch_bounds__(256, 2) void k_mm(
    const __half* __restrict__ A, const __half* __restrict__ B,
    const float* __restrict__ bias, const float* __restrict__ resi,
    float* __restrict__ C, __half* __restrict__ Ch,
    int M, int N, int K)
{
    extern __shared__ char smc[];
    const uint32_t sb = smem_u32(smc);
    const int tid = threadIdx.x, lane = tid & 31, wid = tid >> 5;
    const int warp_m = wid & 3, warp_n = wid >> 2;
    const int bm = blockIdx.y * 128, bn = blockIdx.x * 128;
    const int Kd8 = K >> 3, nch = K >> 6;

    const uint4* A4 = (const uint4*)A;
    const uint4* B4 = (const uint4*)B;

    float acc[2][8][4];
    #pragma unroll
    for (int a = 0; a < 2; a++)
        #pragma unroll
        for (int b = 0; b < 8; b++)
            #pragma unroll
            for (int c = 0; c < 4; c++) acc[a][b][c] = 0.f;

    auto load_chunk = [&](int i, int s) {
        int k0d8 = i << 3;
        uint32_t stg = sb + s * STG_BYTES;
        #pragma unroll
        for (int t = tid; t < 2048; t += 256) {
            int mat = t >> 10, r = (t >> 3) & 127, c8 = t & 7;
            uint32_t dst = stg + mat * STG_MAT + r * 144 + c8 * 16;
            if (mat == 0) {
                int grow = bm + r;
                int ok = grow < M;
                const uint4* src = A4 + (size_t)(ok ? grow : 0) * Kd8 + k0d8 + c8;
                cpa16(dst, src, ok ? 16u : 0u);
            } else {
                const uint4* src = B4 + (size_t)(bn + r) * Kd8 + k0d8 + c8;
                cpa16(dst, src, 16u);
            }
        }
        CP_COMMIT();
    };

    load_chunk(0, 0);
    load_chunk(1, 1);

    const uint32_t aoff = (uint32_t)((warp_m * 32 + (lane & 15)) * 144 + ((lane >> 4) << 4));
    const int brow = (lane & 7) + ((lane >> 4) << 3);
    const uint32_t boff = (uint32_t)(STG_MAT + (warp_n * 64 + brow) * 144
                                     + (((lane >> 3) & 1) << 4));

    int s = 0;
    for (int i = 0; i < nch; i++) {
        if (i + 1 < nch) CP_WAIT1(); else CP_WAIT0();
        __syncthreads();
        if (i + 2 < nch) {
            int s2 = s + 2; if (s2 >= 3) s2 -= 3;
            load_chunk(i + 2, s2);
        }
        uint32_t stg = sb + s * STG_BYTES;
        uint32_t aA = stg + aoff, bB = stg + boff;
        #pragma unroll
        for (int k16 = 0; k16 < 4; k16++) {
            uint32_t ah[2][4], bf[4][4];
            #pragma unroll
            for (int mf = 0; mf < 2; mf++)
                LDSM4(ah[mf][0], ah[mf][1], ah[mf][2], ah[mf][3],
                      aA + mf * (16 * 144) + k16 * 32);
            #pragma unroll
            for (int p = 0; p < 4; p++)
                LDSM4(bf[p][0], bf[p][1], bf[p][2], bf[p][3],
                      bB + p * (16 * 144) + k16 * 32);
            #pragma unroll
            for (int p = 0; p < 4; p++)
                #pragma unroll
                for (int sub = 0; sub < 2; sub++)
                    #pragma unroll
                    for (int mf = 0; mf < 2; mf++)
                        MMA16816(acc[mf][p * 2 + sub],
                                 ah[mf][0], ah[mf][1], ah[mf][2], ah[mf][3],
                                 bf[p][2 * sub], bf[p][2 * sub + 1]);
        }
        s++; if (s == 3) s = 0;
    }

    // ---- epilogue (paired stores) ----
    const int qrow = lane >> 2;
    #pragma unroll
    for (int mf = 0; mf < 2; mf++) {
        #pragma unroll
        for (int nf = 0; nf < 8; nf++) {
            int col = bn + warp_n * 64 + nf * 8 + ((lane & 3) << 1);
            float b0 = 0.f, b1 = 0.f;
            if (BIAS) { b0 = bias[col]; b1 = bias[col + 1]; }
            #pragma unroll
            for (int er = 0; er < 2; er++) {
                int row = bm + warp_m * 32 + mf * 16 + qrow + er * 8;
                if (row >= M) continue;
                float v0 = acc[mf][nf][er * 2 + 0] + b0;
                float v1 = acc[mf][nf][er * 2 + 1] + b1;
                if (GELU_) {
                    v0 = v0 / (1.f + __expf(-1.702f * v0));
                    v1 = v1 / (1.f + __expf(-1.702f * v1));
                }
                if (RES) {
                    float2 rr = *(const float2*)(resi + (size_t)row * N + col);
                    v0 += rr.x; v1 += rr.y;
                }
                if (F16O) {
                    *(__half2*)(Ch + (size_t)row * N + col) = __floats2half2_rn(v0, v1);
                } else {
                    float2 o; o.x = v0; o.y = v1;
                    *(float2*)(C + (size_t)row * N + col) = o;
                }
            }
        }
    }
}

// ------------------------- 13-warp tensor-core attention -------------------
// one CTA per (b, head), 416 threads = 13 warps, ONE q-tile per warp.
#define ATT_SMEM 87552  // Q 208x72 + K 208x72 + Vt 64x216 halves
#define ATT_THR  416

__global__ __launch_bounds__(ATT_THR) void k_attn(const __half* __restrict__ QKV,
                                                  __half* __restrict__ out)
{
    extern __shared__ __half sm[];
    __half* Qs = sm;             // 208 rows x 72 halves (144 B stride)
    __half* Ks = sm + 14976;     // 208 x 72
    __half* Vt = sm + 29952;     // 64 x 216 halves (432 B stride)
    const int bh = blockIdx.x;
    const int b = bh / Hh, h = bh % Hh;
    const int tid = threadIdx.x, lane = tid & 31, wid = tid >> 5;

    // zero ONLY the Vt pad columns (masked keys give P==0 exactly; 0*garbage
    // would poison output only if garbage were NaN/Inf, so pads must be finite)
    for (int i = tid; i < 64 * 19; i += ATT_THR) {
        int d = i / 19, s_ = 197 + i % 19;
        Vt[d * 216 + s_] = __ushort_as_half(0);
    }

    const __half* qp = QKV + (size_t)b * Ss * (3 * Dm) + h * HD;
    const __half2 qscale = __float2half2_rn(0.125f);
    for (int idx = tid; idx < Ss * 8; idx += ATT_THR) {
        int s_ = idx >> 3, c8 = idx & 7;
        const uint4* row = (const uint4*)(qp + (size_t)s_ * (3 * Dm));
        uint4 qv = row[c8];
        uint4 kv = row[Dm / 8 + c8];
        uint4 vv = row[2 * Dm / 8 + c8];
        __half2* q2 = (__half2*)&qv;
        #pragma unroll
        for (int j = 0; j < 4; j++) q2[j] = __hmul2(q2[j], qscale);
        *(uint4*)(Qs + s_ * 72 + c8 * 8) = qv;
        *(uint4*)(Ks + s_ * 72 + c8 * 8) = kv;
        __half* hv = (__half*)&vv;
        #pragma unroll
        for (int j = 0; j < 8; j++) Vt[(c8 * 8 + j) * 216 + s_] = hv[j];
    }
    __syncthreads();

    const uint32_t qsb = smem_u32(Qs), ksb = smem_u32(Ks), vtb = smem_u32(Vt);
    const uint32_t arow = (uint32_t)((lane & 15) * 144 + ((lane >> 4) << 4));
    const uint32_t brow = (uint32_t)(((lane & 7) + ((lane >> 4) << 3)) * 144
                                     + (((lane >> 3) & 1) << 4));
    const uint32_t vrow = (uint32_t)(((lane & 7) + ((lane >> 4) << 3)) * 432
                                     + (((lane >> 3) & 1) << 4));
    const int r = lane >> 2, cq = (lane & 3) << 1;

    const int qt = wid;   // 13 warps -> exactly one q-tile each
    {
        float sacc[26][4];
        #pragma unroll
        for (int f = 0; f < 26; f++)
            #pragma unroll
            for (int e = 0; e < 4; e++) sacc[f][e] = 0.f;
        #pragma unroll
        for (int k16 = 0; k16 < 4; k16++) {
            uint32_t aq0, aq1, aq2, aq3;
            LDSM4(aq0, aq1, aq2, aq3, qsb + qt * (16 * 144) + arow + k16 * 32);
            #pragma unroll
            for (int p = 0; p < 13; p++) {
                uint32_t kb[4];
                LDSM4(kb[0], kb[1], kb[2], kb[3], ksb + p * (16 * 144) + brow + k16 * 32);
                MMA16816(sacc[2 * p],     aq0, aq1, aq2, aq3, kb[0], kb[1]);
                MMA16816(sacc[2 * p + 1], aq0, aq1, aq2, aq3, kb[2], kb[3]);
            }
        }
        #pragma unroll
        for (int f = 0; f < 26; f++) {
            int c0 = 8 * f + cq;
            if (c0 >= Ss)     { sacc[f][0] = -1e30f; sacc[f][2] = -1e30f; }
            if (c0 + 1 >= Ss) { sacc[f][1] = -1e30f; sacc[f][3] = -1e30f; }
        }
        float mx0 = -1e30f, mx1 = -1e30f;
        #pragma unroll
        for (int f = 0; f < 26; f++) {
            mx0 = fmaxf(mx0, fmaxf(sacc[f][0], sacc[f][1]));
            mx1 = fmaxf(mx1, fmaxf(sacc[f][2], sacc[f][3]));
        }
        mx0 = fmaxf(mx0, __shfl_xor_sync(~0u, mx0, 1));
        mx0 = fmaxf(mx0, __shfl_xor_sync(~0u, mx0, 2));
        mx1 = fmaxf(mx1, __shfl_xor_sync(~0u, mx1, 1));
        mx1 = fmaxf(mx1, __shfl_xor_sync(~0u, mx1, 2));
        float sum0 = 0.f, sum1 = 0.f;
        #pragma unroll
        for (int f = 0; f < 26; f++) {
            sacc[f][0] = __expf(sacc[f][0] - mx0);
            sacc[f][1] = __expf(sacc[f][1] - mx0);
            sacc[f][2] = __expf(sacc[f][2] - mx1);
            sacc[f][3] = __expf(sacc[f][3] - mx1);
            sum0 += sacc[f][0] + sacc[f][1];
            sum1 += sacc[f][2] + sacc[f][3];
        }
        sum0 += __shfl_xor_sync(~0u, sum0, 1);
        sum0 += __shfl_xor_sync(~0u, sum0, 2);
        sum1 += __shfl_xor_sync(~0u, sum1, 1);
        sum1 += __shfl_xor_sync(~0u, sum1, 2);
        float inv0 = 1.f / sum0, inv1 = 1.f / sum1;
        uint32_t pa[13][4];
        #pragma unroll
        for (int kk = 0; kk < 13; kk++) {
            __half2 t0 = __floats2half2_rn(sacc[2*kk][0] * inv0,   sacc[2*kk][1] * inv0);
            __half2 t1 = __floats2half2_rn(sacc[2*kk][2] * inv1,   sacc[2*kk][3] * inv1);
            __half2 t2 = __floats2half2_rn(sacc[2*kk+1][0] * inv0, sacc[2*kk+1][1] * inv0);
            __half2 t3 = __floats2half2_rn(sacc[2*kk+1][2] * inv1, sacc[2*kk+1][3] * inv1);
            pa[kk][0] = *(uint32_t*)&t0;
            pa[kk][1] = *(uint32_t*)&t1;
            pa[kk][2] = *(uint32_t*)&t2;
            pa[kk][3] = *(uint32_t*)&t3;
        }
        float oacc[8][4];
        #pragma unroll
        for (int f = 0; f < 8; f++)
            #pragma unroll
            for (int e = 0; e < 4; e++) oacc[f][e] = 0.f;
        #pragma unroll
        for (int kk = 0; kk < 13; kk++) {
            #pragma unroll
            for (int pv = 0; pv < 4; pv++) {
                uint32_t vb[4];
                LDSM4(vb[0], vb[1], vb[2], vb[3], vtb + pv * (16 * 432) + vrow + kk * 32);
                MMA16816(oacc[2 * pv],     pa[kk][0], pa[kk][1], pa[kk][2], pa[kk][3],
                         vb[0], vb[1]);
                MMA16816(oacc[2 * pv + 1], pa[kk][0], pa[kk][1], pa[kk][2], pa[kk][3],
                         vb[2], vb[3]);
            }
        }
        #pragma unroll
        for (int f = 0; f < 8; f++) {
            int d = 8 * f + cq;
            #pragma unroll
            for (int er = 0; er < 2; er++) {
                int q = qt * 16 + r + er * 8;
                if (q < Ss)
                    *(__half2*)(out + ((size_t)(b * Ss + q)) * Dm + h * HD + d)
                        = __floats2half2_rn(oacc[f][er * 2], oacc[f][er * 2 + 1]);
            }
        }
    }
}

// ------------------------- warp-per-row LayerNorm --------------------------
template<bool F16>
__global__ __launch_bounds__(256) void k_ln(
    const float* __restrict__ in, float* __restrict__ outf, __half* __restrict__ oh,
    const float* __restrict__ sc, const float* __restrict__ bi,
    long in_stride, long out_stride, int nrows)
{
    int row = blockIdx.x * 8 + (threadIdx.x >> 5);
    if (row >= nrows) return;
    int lane = threadIdx.x & 31;
    const float4* ip = (const float4*)(in + (size_t)row * in_stride);
    float4 v[6];
    float s = 0.f, sq = 0.f;
    #pragma unroll
    for (int j = 0; j < 6; j++) {
        v[j] = ip[j * 32 + lane];
        s  += v[j].x + v[j].y + v[j].z + v[j].w;
        sq += v[j].x*v[j].x + v[j].y*v[j].y + v[j].z*v[j].z + v[j].w*v[j].w;
    }
    #pragma unroll
    for (int o = 16; o > 0; o >>= 1) {
        s  += __shfl_xor_sync(~0u, s, o);
        sq += __shfl_xor_sync(~0u, sq, o);
    }
    float mean = s * (1.f / Dm);
    float var  = sq * (1.f / Dm) - mean * mean;
    float r = rsqrtf(var + 1e-5f);
    const float4* sc4 = (const float4*)sc;
    const float4* bi4 = (const float4*)bi;
    #pragma unroll
    for (int j = 0; j < 6; j++) {
        float4 g = sc4[j * 32 + lane], be = bi4[j * 32 + lane];
        float y0 = (v[j].x - mean) * r * g.x + be.x;
        float y1 = (v[j].y - mean) * r * g.y + be.y;
        float y2 = (v[j].z - mean) * r * g.z + be.z;
        float y3 = (v[j].w - mean) * r * g.w + be.w;
        if (F16) {
            __half2 h0 = __floats2half2_rn(y0, y1);
            __half2 h1 = __floats2half2_rn(y2, y3);
            uint2 pk; pk.x = *(uint32_t*)&h0; pk.y = *(uint32_t*)&h1;
            ((uint2*)(oh + (size_t)row * out_stride))[j * 32 + lane] = pk;
        } else {
            float4 o; o.x = y0; o.y = y1; o.z = y2; o.w = y3;
            ((float4*)(outf + (size_t)row * out_stride))[j * 32 + lane] = o;
        }
    }
}

// --------------- fused assemble (cls+patch+pos) + ln_pre -> x --------------
__global__ __launch_bounds__(256) void k_asmln(
    const float* __restrict__ pe, const float* __restrict__ cls,
    const float* __restrict__ pos,
    const float* __restrict__ sc, const float* __restrict__ bi,
    float* __restrict__ x)
{
    int t = blockIdx.x * 8 + (threadIdx.x >> 5);
    if (t >= NTOK) return;
    int lane = threadIdx.x & 31;
    int s_ = t % Ss, b = t / Ss;
    const float4* src4 = (s_ == 0) ? (const float4*)cls
                       : (const float4*)(pe + (size_t)(b * NPATCH + s_ - 1) * Dm);
    const float4* pos4 = (const float4*)(pos + (size_t)s_ * Dm);
    float4 v[6];
    float s = 0.f, sq = 0.f;
    #pragma unroll
    for (int j = 0; j < 6; j++) {
        float4 a = src4[j * 32 + lane], p = pos4[j * 32 + lane];
        v[j].x = a.x + p.x; v[j].y = a.y + p.y; v[j].z = a.z + p.z; v[j].w = a.w + p.w;
        s  += v[j].x + v[j].y + v[j].z + v[j].w;
        sq += v[j].x*v[j].x + v[j].y*v[j].y + v[j].z*v[j].z + v[j].w*v[j].w;
    }
    #pragma unroll
    for (int o = 16; o > 0; o >>= 1) {
        s  += __shfl_xor_sync(~0u, s, o);
        sq += __shfl_xor_sync(~0u, sq, o);
    }
    float mean = s * (1.f / Dm);
    float var  = sq * (1.f / Dm) - mean * mean;
    float r = rsqrtf(var + 1e-5f);
    const float4* sc4 = (const float4*)sc;
    const float4* bi4 = (const float4*)bi;
    #pragma unroll
    for (int j = 0; j < 6; j++) {
        float4 g = sc4[j * 32 + lane], be = bi4[j * 32 + lane];
        float4 o;
        o.x = (v[j].x - mean) * r * g.x + be.x;
        o.y = (v[j].y - mean) * r * g.y + be.y;
        o.z = (v[j].z - mean) * r * g.z + be.z;
        o.w = (v[j].w - mean) * r * g.w + be.w;
        ((float4*)(x + (size_t)t * Dm))[j * 32 + lane] = o;
    }
}

// ------------------------- head: cls_ln @ vis_proj -------------------------
__global__ __launch_bounds__(512) void k_head(const float* __restrict__ cls,
                                              const float* __restrict__ Wp,
                                              float* __restrict__ out)
{
    __shared__ float row[Dm];
    int b = blockIdx.x;
    for (int i = threadIdx.x; i < Dm; i += 512) row[i] = cls[(size_t)b * Dm + i];
    __syncthreads();
    int o = threadIdx.x;
    float acc = 0.f;
    for (int d = 0; d < Dm; d++) acc += row[d] * Wp[(size_t)d * Oo + o];
    out[(size_t)b * Oo + o] = acc;
}

// ---------------------------------------------------------------------------
extern "C" void kernel_launch(void* const* d_in, const int* in_sizes, int n_in,
                              void* d_out, int out_size)
{
    const float* images   = (const float*)d_in[0];
    const float* conv_w   = (const float*)d_in[1];
    const float* cls_emb  = (const float*)d_in[2];
    const float* pos_emb  = (const float*)d_in[3];
    const float* ln_pre_s = (const float*)d_in[4];
    const float* ln_pre_b = (const float*)d_in[5];
    const float* ln1_s    = (const float*)d_in[6];
    const float* ln1_b    = (const float*)d_in[7];
    const float* qkv_w    = (const float*)d_in[8];
    const float* qkv_b    = (const float*)d_in[9];
    const float* out_w    = (const float*)d_in[10];
    const float* out_b    = (const float*)d_in[11];
    const float* ln2_s    = (const float*)d_in[12];
    const float* ln2_b    = (const float*)d_in[13];
    const float* fc_w     = (const float*)d_in[14];
    const float* fc_b     = (const float*)d_in[15];
    const float* proj_w   = (const float*)d_in[16];
    const float* proj_b   = (const float*)d_in[17];
    const float* lnp_s    = (const float*)d_in[18];
    const float* lnp_b    = (const float*)d_in[19];
    const float* vis_proj = (const float*)d_in[20];
    float* outp = (float*)d_out;

    __half *w, *xp, *h, *qkvh, *ao, *mlp;
    float *pe, *x, *cls;
    cudaGetSymbolAddress((void**)&w,    g_w);
    cudaGetSymbolAddress((void**)&xp,   g_xp);
    cudaGetSymbolAddress((void**)&pe,   g_pe);
    cudaGetSymbolAddress((void**)&x,    g_x);
    cudaGetSymbolAddress((void**)&h,    g_h);
    cudaGetSymbolAddress((void**)&qkvh, g_qkvh);
    cudaGetSymbolAddress((void**)&ao,   g_ao);
    cudaGetSymbolAddress((void**)&mlp,  g_mlp);
    cudaGetSymbolAddress((void**)&cls,  g_cls);

    cudaFuncSetAttribute(k_mm<false,false,false,false>, cudaFuncAttributeMaxDynamicSharedMemorySize, MM_SMEM);
    cudaFuncSetAttribute(k_mm<true, false,false,true >, cudaFuncAttributeMaxDynamicSharedMemorySize, MM_SMEM);
    cudaFuncSetAttribute(k_mm<true, true, false,false>, cudaFuncAttributeMaxDynamicSharedMemorySize, MM_SMEM);
    cudaFuncSetAttribute(k_mm<true, false,true, true >, cudaFuncAttributeMaxDynamicSharedMemorySize, MM_SMEM);
    cudaFuncSetAttribute(k_attn, cudaFuncAttributeMaxDynamicSharedMemorySize, ATT_SMEM);

    // ---- all weights fp32 -> fp16, one launch ----
    k_cvt_all<<<(F4_TOT + 255) / 256, 256>>>(
        (const float4*)conv_w, (const float4*)qkv_w, (const float4*)out_w,
        (const float4*)fc_w, (const float4*)proj_w, (__half2*)w);

    // ---- stem ----
    k_patchify<<<(NPROW * Dm + 255) / 256, 256>>>(images, xp);
    k_mm<false,false,false,false><<<dim3(Dm / 128, (NPROW + 127) / 128), 256, MM_SMEM>>>(
        xp, w + OFF_CONV, nullptr, nullptr, pe, nullptr, NPROW, Dm, Dm);
    k_asmln<<<(NTOK + 7) / 8, 256>>>(pe, cls_emb, pos_emb, ln_pre_s, ln_pre_b, x);

    // ---- transformer layers ----
    for (int l = 0; l < Ll; l++) {
        const float* l1s = ln1_s + (size_t)l * Dm;
        const float* l1b = ln1_b + (size_t)l * Dm;
        const float* qb  = qkv_b + (size_t)l * 3 * Dm;
        const float* ob  = out_b + (size_t)l * Dm;
        const float* l2s = ln2_s + (size_t)l * Dm;
        const float* l2b = ln2_b + (size_t)l * Dm;
        const float* fb  = fc_b  + (size_t)l * Ff;
        const float* pb  = proj_b + (size_t)l * Dm;
        const __half* qw = w + OFF_QKV  + (size_t)l * 2304 * 768;
        const __half* ow = w + OFF_OUT  + (size_t)l * 768 * 768;
        const __half* fw = w + OFF_FC   + (size_t)l * 3072 * 768;
        const __half* pw = w + OFF_PROJ + (size_t)l * 768 * 3072;

        k_ln<true><<<(NTOK + 7) / 8, 256>>>(x, nullptr, h, l1s, l1b, Dm, Dm, NTOK);
        k_mm<true,false,false,true><<<dim3(3 * Dm / 128, (NTOK + 127) / 128), 256, MM_SMEM>>>(
            h, qw, qb, nullptr, nullptr, qkvh, NTOK, 3 * Dm, Dm);
        k_attn<<<Bsz * Hh, ATT_THR, ATT_SMEM>>>(qkvh, ao);
        k_mm<true,true,false,false><<<dim3(Dm / 128, (NTOK + 127) / 128), 256, MM_SMEM>>>(
            ao, ow, ob, x, x, nullptr, NTOK, Dm, Dm);
        k_ln<true><<<(NTOK + 7) / 8, 256>>>(x, nullptr, h, l2s, l2b, Dm, Dm, NTOK);
        k_mm<true,false,true,true><<<dim3(Ff / 128, (NTOK + 127) / 128), 256, MM_SMEM>>>(
            h, fw, fb, nullptr, nullptr, mlp, NTOK, Ff, Dm);
        k_mm<true,true,false,false><<<dim3(Dm / 128, (NTOK + 127) / 128), 256, MM_SMEM>>>(
            mlp, pw, pb, x, x, nullptr, NTOK, Dm, Ff);
    }

    // ---- head ----
    k_ln<false><<<4, 256>>>(x, cls, nullptr, lnp_s, lnp_b, (long)Ss * Dm, Dm, Bsz);
    k_head<<<Bsz, 512>>>(cls, vis_proj, outp);
}

// round 16
// speedup vs baseline: 1.0476x; 1.0091x over previous
#include <cuda_runtime.h>
#include <cuda_fp16.h>
#include <math.h>
#include <cstdint>

// ---------------------------------------------------------------------------
// CLIP ViT-B/16 visual tower on GB300 — 1-term fp16 mma.sync GEMMs (occ=2)
// + 13-warp attention with row-major V + ldmatrix.trans (conflict-free fill).
// ---------------------------------------------------------------------------

#define Bsz 32
#define Dm  768
#define Hh  12
#define HD  64
#define Ff  3072
#define Ll  12
#define Ss  197
#define Oo  512
#define NPATCH 196
#define NTOK (Bsz * Ss)        // 6304
#define NPROW (Bsz * NPATCH)   // 6272

// ------------------------- helpers -----------------------------------------
__device__ __forceinline__ uint32_t smem_u32(const void* p) {
    uint32_t a;
    asm("{ .reg .u64 t; cvta.to.shared.u64 t, %1; cvt.u32.u64 %0, t; }"
        : "=r"(a) : "l"(p));
    return a;
}
__device__ __forceinline__ void cpa16(uint32_t dst, const void* src, uint32_t vsz) {
    asm volatile("cp.async.cg.shared.global [%0], [%1], 16, %2;"
                 :: "r"(dst), "l"(src), "r"(vsz) : "memory");
}
#define CP_COMMIT() asm volatile("cp.async.commit_group;" ::: "memory")
#define CP_WAIT0()  asm volatile("cp.async.wait_group 0;" ::: "memory")
#define CP_WAIT1()  asm volatile("cp.async.wait_group 1;" ::: "memory")

#define MMA16816(c, a0, a1, a2, a3, b0, b1) \
    asm volatile("mma.sync.aligned.m16n8k16.row.col.f32.f16.f16.f32 " \
        "{%0,%1,%2,%3}, {%4,%5,%6,%7}, {%8,%9}, {%0,%1,%2,%3};" \
        : "+f"((c)[0]), "+f"((c)[1]), "+f"((c)[2]), "+f"((c)[3]) \
        : "r"(a0), "r"(a1), "r"(a2), "r"(a3), "r"(b0), "r"(b1))

#define LDSM4(r0, r1, r2, r3, addr) \
    asm volatile("ldmatrix.sync.aligned.m8n8.x4.shared.b16 {%0,%1,%2,%3}, [%4];" \
        : "=r"(r0), "=r"(r1), "=r"(r2), "=r"(r3) : "r"(addr))

#define LDSM4T(r0, r1, r2, r3, addr) \
    asm volatile("ldmatrix.sync.aligned.m8n8.x4.trans.shared.b16 {%0,%1,%2,%3}, [%4];" \
        : "=r"(r0), "=r"(r1), "=r"(r2), "=r"(r3) : "r"(addr))

// ------------------------- scratch (static device globals) -----------------
#define OFF_CONV 0ul
#define OFF_QKV  589824ul
#define OFF_OUT  21823488ul
#define OFF_FC   28901376ul
#define OFF_PROJ 57212928ul
#define WTOT     85524480ul

__device__ __align__(16) __half g_w[WTOT];         // fp16 weights
__device__ __align__(16) __half g_xp[NPROW * Dm];  // fp16 patch matrix
__device__ __align__(16) float g_pe[NPROW * Dm];
__device__ __align__(16) float g_x [NTOK * Dm];    // fp32 residual stream
__device__ __align__(16) __half g_h[NTOK * Dm];    // fp16 LN output
__device__ __align__(16) __half g_qkvh[NTOK * 3 * Dm]; // fp16 qkv
__device__ __align__(16) __half g_ao[NTOK * Dm];   // fp16 attn out
__device__ __align__(16) __half g_mlp[NTOK * Ff];  // fp16 mlp hidden
__device__ __align__(16) float g_cls[Bsz * Dm];

// --------------- all weights fp32 -> fp16, one kernel ----------------------
#define F4_CONV (589824 / 4)
#define F4_QKV  (21233664 / 4)
#define F4_OUT  (7077888 / 4)
#define F4_FC   (28311552 / 4)
#define F4_PROJ (28311552 / 4)
#define F4_TOT  (F4_CONV + F4_QKV + F4_OUT + F4_FC + F4_PROJ)

__global__ __launch_bounds__(256) void k_cvt_all(
    const float4* __restrict__ s_conv, const float4* __restrict__ s_qkv,
    const float4* __restrict__ s_out,  const float4* __restrict__ s_fc,
    const float4* __restrict__ s_proj, __half2* __restrict__ w)
{
    long i = (long)blockIdx.x * blockDim.x + threadIdx.x;
    if (i >= F4_TOT) return;
    const float4* src;
    long loc; unsigned long dst;
    if (i < F4_CONV) { src = s_conv; loc = i; dst = OFF_CONV / 2 + loc * 2; }
    else if (i < F4_CONV + F4_QKV) { src = s_qkv; loc = i - F4_CONV; dst = OFF_QKV / 2 + loc * 2; }
    else if (i < F4_CONV + F4_QKV + F4_OUT) { src = s_out; loc = i - F4_CONV - F4_QKV; dst = OFF_OUT / 2 + loc * 2; }
    else if (i < F4_CONV + F4_QKV + F4_OUT + F4_FC) { src = s_fc; loc = i - F4_CONV - F4_QKV - F4_OUT; dst = OFF_FC / 2 + loc * 2; }
    else { src = s_proj; loc = i - F4_CONV - F4_QKV - F4_OUT - F4_FC; dst = OFF_PROJ / 2 + loc * 2; }
    float4 v = src[loc];
    w[dst]     = __floats2half2_rn(v.x, v.y);
    w[dst + 1] = __floats2half2_rn(v.z, v.w);
}

// ------------------------- patchify + normalize -> fp16 --------------------
__global__ void k_patchify(const float* __restrict__ img, __half* __restrict__ xh)
{
    const float mean[3] = {0.48145466f, 0.4578275f, 0.40821073f};
    const float istd[3] = {1.f/0.26862954f, 1.f/0.26130258f, 1.f/0.27577711f};
    int idx = blockIdx.x * blockDim.x + threadIdx.x;
    if (idx >= NPROW * Dm) return;
    int col = idx % Dm;
    int row = idx / Dm;
    int b  = row / NPATCH;
    int p  = row % NPATCH;
    int py = p / 14, px = p % 14;
    int c  = col >> 8;
    int rem = col & 255;
    int ph = rem >> 4, pw = rem & 15;
    float v = img[(((size_t)b * 3 + c) * 224 + py * 16 + ph) * 224 + px * 16 + pw];
    xh[idx] = __float2half((v - mean[c]) * istd[c]);
}

// ------------------------- mma.sync fp16 GEMM (occ=2) ----------------------
#define STG_MAT   18432            // 128 rows * 144 B
#define STG_BYTES 36864            // 2 matrices (A, B)
#define MM_SMEM   (3 * STG_BYTES)  // 110592

template<bool BIAS, bool RES, bool GELU_, bool F16O>
__global__ __launch_bounds__(256, 2) void k_mm(
    const __half* __restrict__ A, const __half* __restrict__ B,
    const float* __restrict__ bias, const float* __restrict__ resi,
    float* __restrict__ C, __half* __restrict__ Ch,
    int M, int N, int K)
{
    extern __shared__ char smc[];
    const uint32_t sb = smem_u32(smc);
    const int tid = threadIdx.x, lane = tid & 31, wid = tid >> 5;
    const int warp_m = wid & 3, warp_n = wid >> 2;
    const int bm = blockIdx.y * 128, bn = blockIdx.x * 128;
    const int Kd8 = K >> 3, nch = K >> 6;

    const uint4* A4 = (const uint4*)A;
    const uint4* B4 = (const uint4*)B;

    float acc[2][8][4];
    #pragma unroll
    for (int a = 0; a < 2; a++)
        #pragma unroll
        for (int b = 0; b < 8; b++)
            #pragma unroll
            for (int c = 0; c < 4; c++) acc[a][b][c] = 0.f;

    auto load_chunk = [&](int i, int s) {
        int k0d8 = i << 3;
        uint32_t stg = sb + s * STG_BYTES;
        #pragma unroll
        for (int t = tid; t < 2048; t += 256) {
            int mat = t >> 10, r = (t >> 3) & 127, c8 = t & 7;
            uint32_t dst = stg + mat * STG_MAT + r * 144 + c8 * 16;
            if (mat == 0) {
                int grow = bm + r;
                int ok = grow < M;
                const uint4* src = A4 + (size_t)(ok ? grow : 0) * Kd8 + k0d8 + c8;
                cpa16(dst, src, ok ? 16u : 0u);
            } else {
                const uint4* src = B4 + (size_t)(bn + r) * Kd8 + k0d8 + c8;
                cpa16(dst, src, 16u);
            }
        }
        CP_COMMIT();
    };

    load_chunk(0, 0);
    load_chunk(1, 1);

    const uint32_t aoff = (uint32_t)((warp_m * 32 + (lane & 15)) * 144 + ((lane >> 4) << 4));
    const int brow = (lane & 7) + ((lane >> 4) << 3);
    const uint32_t boff = (uint32_t)(STG_MAT + (warp_n * 64 + brow) * 144
                                     + (((lane >> 3) & 1) << 4));

    int s = 0;
    for (int i = 0; i < nch; i++) {
        if (i + 1 < nch) CP_WAIT1(); else CP_WAIT0();
        __syncthreads();
        if (i + 2 < nch) {
            int s2 = s + 2; if (s2 >= 3) s2 -= 3;
            load_chunk(i + 2, s2);
        }
        uint32_t stg = sb + s * STG_BYTES;
        uint32_t aA = stg + aoff, bB = stg + boff;
        #pragma unroll
        for (int k16 = 0; k16 < 4; k16++) {
            uint32_t ah[2][4], bf[4][4];
            #pragma unroll
            for (int mf = 0; mf < 2; mf++)
                LDSM4(ah[mf][0], ah[mf][1], ah[mf][2], ah[mf][3],
                      aA + mf * (16 * 144) + k16 * 32);
            #pragma unroll
            for (int p = 0; p < 4; p++)
                LDSM4(bf[p][0], bf[p][1], bf[p][2], bf[p][3],
                      bB + p * (16 * 144) + k16 * 32);
            #pragma unroll
            for (int p = 0; p < 4; p++)
                #pragma unroll
                for (int sub = 0; sub < 2; sub++)
                    #pragma unroll
                    for (int mf = 0; mf < 2; mf++)
                        MMA16816(acc[mf][p * 2 + sub],
                                 ah[mf][0], ah[mf][1], ah[mf][2], ah[mf][3],
                                 bf[p][2 * sub], bf[p][2 * sub + 1]);
        }
        s++; if (s == 3) s = 0;
    }

    // ---- epilogue (paired stores) ----
    const int qrow = lane >> 2;
    #pragma unroll
    for (int mf = 0; mf < 2; mf++) {
        #pragma unroll
        for (int nf = 0; nf < 8; nf++) {
            int col = bn + warp_n * 64 + nf * 8 + ((lane & 3) << 1);
            float b0 = 0.f, b1 = 0.f;
            if (BIAS) { b0 = bias[col]; b1 = bias[col + 1]; }
            #pragma unroll
            for (int er = 0; er < 2; er++) {
                int row = bm + warp_m * 32 + mf * 16 + qrow + er * 8;
                if (row >= M) continue;
                float v0 = acc[mf][nf][er * 2 + 0] + b0;
                float v1 = acc[mf][nf][er * 2 + 1] + b1;
                if (GELU_) {
                    v0 = v0 / (1.f + __expf(-1.702f * v0));
                    v1 = v1 / (1.f + __expf(-1.702f * v1));
                }
                if (RES) {
                    float2 rr = *(const float2*)(resi + (size_t)row * N + col);
                    v0 += rr.x; v1 += rr.y;
                }
                if (F16O) {
                    *(__half2*)(Ch + (size_t)row * N + col) = __floats2half2_rn(v0, v1);
                } else {
                    float2 o; o.x = v0; o.y = v1;
                    *(float2*)(C + (size_t)row * N + col) = o;
                }
            }
        }
    }
}

// ------------------------- 13-warp tensor-core attention -------------------
// one CTA per (b, head), 416 threads = 13 warps, ONE q-tile per warp.
// V stored row-major [s][d] like K; PV B-fragments via ldmatrix.trans.
#define ATT_SMEM 89856  // 3 x (208 rows x 72 halves)
#define ATT_THR  416

__global__ __launch_bounds__(ATT_THR) void k_attn(const __half* __restrict__ QKV,
                                                  __half* __restrict__ out)
{
    extern __shared__ __half sm[];
    __half* Qs = sm;             // 208 x 72 (144 B stride)
    __half* Ks = sm + 14976;     // 208 x 72
    __half* Vs = sm + 29952;     // 208 x 72 (row-major, same as K)
    const int bh = blockIdx.x;
    const int b = bh / Hh, h = bh % Hh;
    const int tid = threadIdx.x, lane = tid & 31, wid = tid >> 5;

    // zero V pad rows 197..207 (P==0 for masked keys; pads must be finite)
    for (int i = tid; i < 11 * 9; i += ATT_THR) {
        int s_ = 197 + i / 9, c8 = i % 9;
        if (c8 < 9)
            *(uint4*)(Vs + s_ * 72 + c8 * 8) = make_uint4(0, 0, 0, 0);
    }

    const __half* qp = QKV + (size_t)b * Ss * (3 * Dm) + h * HD;
    const __half2 qscale = __float2half2_rn(0.125f);
    for (int idx = tid; idx < Ss * 8; idx += ATT_THR) {
        int s_ = idx >> 3, c8 = idx & 7;
        const uint4* row = (const uint4*)(qp + (size_t)s_ * (3 * Dm));
        uint4 qv = row[c8];
        uint4 kv = row[Dm / 8 + c8];
        uint4 vv = row[2 * Dm / 8 + c8];
        __half2* q2 = (__half2*)&qv;
        #pragma unroll
        for (int j = 0; j < 4; j++) q2[j] = __hmul2(q2[j], qscale);
        *(uint4*)(Qs + s_ * 72 + c8 * 8) = qv;
        *(uint4*)(Ks + s_ * 72 + c8 * 8) = kv;
        *(uint4*)(Vs + s_ * 72 + c8 * 8) = vv;
    }
    __syncthreads();

    const uint32_t qsb = smem_u32(Qs), ksb = smem_u32(Ks), vsb = smem_u32(Vs);
    const uint32_t arow = (uint32_t)((lane & 15) * 144 + ((lane >> 4) << 4));
    const uint32_t brow = (uint32_t)(((lane & 7) + ((lane >> 4) << 3)) * 144
                                     + (((lane >> 3) & 1) << 4));
    // trans-B addressing: rows = s (k dim), cols = d (n dim)
    const uint32_t vrow = (uint32_t)(((lane & 7) + (((lane >> 3) & 1) << 3)) * 144
                                     + ((lane >> 4) << 4));
    const int r = lane >> 2, cq = (lane & 3) << 1;

    const int qt = wid;   // 13 warps -> exactly one q-tile each
    {
        float sacc[26][4];
        #pragma unroll
        for (int f = 0; f < 26; f++)
            #pragma unroll
            for (int e = 0; e < 4; e++) sacc[f][e] = 0.f;
        #pragma unroll
        for (int k16 = 0; k16 < 4; k16++) {
            uint32_t aq0, aq1, aq2, aq3;
            LDSM4(aq0, aq1, aq2, aq3, qsb + qt * (16 * 144) + arow + k16 * 32);
            #pragma unroll
            for (int p = 0; p < 13; p++) {
                uint32_t kb[4];
                LDSM4(kb[0], kb[1], kb[2], kb[3], ksb + p * (16 * 144) + brow + k16 * 32);
                MMA16816(sacc[2 * p],     aq0, aq1, aq2, aq3, kb[0], kb[1]);
                MMA16816(sacc[2 * p + 1], aq0, aq1, aq2, aq3, kb[2], kb[3]);
            }
        }
        #pragma unroll
        for (int f = 0; f < 26; f++) {
            int c0 = 8 * f + cq;
            if (c0 >= Ss)     { sacc[f][0] = -1e30f; sacc[f][2] = -1e30f; }
            if (c0 + 1 >= Ss) { sacc[f][1] = -1e30f; sacc[f][3] = -1e30f; }
        }
        float mx0 = -1e30f, mx1 = -1e30f;
        #pragma unroll
        for (int f = 0; f < 26; f++) {
            mx0 = fmaxf(mx0, fmaxf(sacc[f][0], sacc[f][1]));
            mx1 = fmaxf(mx1, fmaxf(sacc[f][2], sacc[f][3]));
        }
        mx0 = fmaxf(mx0, __shfl_xor_sync(~0u, mx0, 1));
        mx0 = fmaxf(mx0, __shfl_xor_sync(~0u, mx0, 2));
        mx1 = fmaxf(mx1, __shfl_xor_sync(~0u, mx1, 1));
        mx1 = fmaxf(mx1, __shfl_xor_sync(~0u, mx1, 2));
        float sum0 = 0.f, sum1 = 0.f;
        #pragma unroll
        for (int f = 0; f < 26; f++) {
            sacc[f][0] = __expf(sacc[f][0] - mx0);
            sacc[f][1] = __expf(sacc[f][1] - mx0);
            sacc[f][2] = __expf(sacc[f][2] - mx1);
            sacc[f][3] = __expf(sacc[f][3] - mx1);
            sum0 += sacc[f][0] + sacc[f][1];
            sum1 += sacc[f][2] + sacc[f][3];
        }
        sum0 += __shfl_xor_sync(~0u, sum0, 1);
        sum0 += __shfl_xor_sync(~0u, sum0, 2);
        sum1 += __shfl_xor_sync(~0u, sum1, 1);
        sum1 += __shfl_xor_sync(~0u, sum1, 2);
        float inv0 = 1.f / sum0, inv1 = 1.f / sum1;
        uint32_t pa[13][4];
        #pragma unroll
        for (int kk = 0; kk < 13; kk++) {
            __half2 t0 = __floats2half2_rn(sacc[2*kk][0] * inv0,   sacc[2*kk][1] * inv0);
            __half2 t1 = __floats2half2_rn(sacc[2*kk][2] * inv1,   sacc[2*kk][3] * inv1);
            __half2 t2 = __floats2half2_rn(sacc[2*kk+1][0] * inv0, sacc[2*kk+1][1] * inv0);
            __half2 t3 = __floats2half2_rn(sacc[2*kk+1][2] * inv1, sacc[2*kk+1][3] * inv1);
            pa[kk][0] = *(uint32_t*)&t0;
            pa[kk][1] = *(uint32_t*)&t1;
            pa[kk][2] = *(uint32_t*)&t2;
            pa[kk][3] = *(uint32_t*)&t3;
        }
        float oacc[8][4];
        #pragma unroll
        for (int f = 0; f < 8; f++)
            #pragma unroll
            for (int e = 0; e < 4; e++) oacc[f][e] = 0.f;
        #pragma unroll
        for (int kk = 0; kk < 13; kk++) {
            #pragma unroll
            for (int pv = 0; pv < 4; pv++) {
                uint32_t vb[4];
                LDSM4T(vb[0], vb[1], vb[2], vb[3],
                       vsb + kk * (16 * 144) + pv * 32 + vrow);
                MMA16816(oacc[2 * pv],     pa[kk][0], pa[kk][1], pa[kk][2], pa[kk][3],
                         vb[0], vb[1]);
                MMA16816(oacc[2 * pv + 1], pa[kk][0], pa[kk][1], pa[kk][2], pa[kk][3],
                         vb[2], vb[3]);
            }
        }
        #pragma unroll
        for (int f = 0; f < 8; f++) {
            int d = 8 * f + cq;
            #pragma unroll
            for (int er = 0; er < 2; er++) {
                int q = qt * 16 + r + er * 8;
                if (q < Ss)
                    *(__half2*)(out + ((size_t)(b * Ss + q)) * Dm + h * HD + d)
                        = __floats2half2_rn(oacc[f][er * 2], oacc[f][er * 2 + 1]);
            }
        }
    }
}

// ------------------------- warp-per-row LayerNorm --------------------------
template<bool F16>
__global__ __launch_bounds__(256) void k_ln(
    const float* __restrict__ in, float* __restrict__ outf, __half* __restrict__ oh,
    const float* __restrict__ sc, const float* __restrict__ bi,
    long in_stride, long out_stride, int nrows)
{
    int row = blockIdx.x * 8 + (threadIdx.x >> 5);
    if (row >= nrows) return;
    int lane = threadIdx.x & 31;
    const float4* ip = (const float4*)(in + (size_t)row * in_stride);
    float4 v[6];
    float s = 0.f, sq = 0.f;
    #pragma unroll
    for (int j = 0; j < 6; j++) {
        v[j] = ip[j * 32 + lane];
        s  += v[j].x + v[j].y + v[j].z + v[j].w;
        sq += v[j].x*v[j].x + v[j].y*v[j].y + v[j].z*v[j].z + v[j].w*v[j].w;
    }
    #pragma unroll
    for (int o = 16; o > 0; o >>= 1) {
        s  += __shfl_xor_sync(~0u, s, o);
        sq += __shfl_xor_sync(~0u, sq, o);
    }
    float mean = s * (1.f / Dm);
    float var  = sq * (1.f / Dm) - mean * mean;
    float r = rsqrtf(var + 1e-5f);
    const float4* sc4 = (const float4*)sc;
    const float4* bi4 = (const float4*)bi;
    #pragma unroll
    for (int j = 0; j < 6; j++) {
        float4 g = sc4[j * 32 + lane], be = bi4[j * 32 + lane];
        float y0 = (v[j].x - mean) * r * g.x + be.x;
        float y1 = (v[j].y - mean) * r * g.y + be.y;
        float y2 = (v[j].z - mean) * r * g.z + be.z;
        float y3 = (v[j].w - mean) * r * g.w + be.w;
        if (F16) {
            __half2 h0 = __floats2half2_rn(y0, y1);
            __half2 h1 = __floats2half2_rn(y2, y3);
            uint2 pk; pk.x = *(uint32_t*)&h0; pk.y = *(uint32_t*)&h1;
            ((uint2*)(oh + (size_t)row * out_stride))[j * 32 + lane] = pk;
        } else {
            float4 o; o.x = y0; o.y = y1; o.z = y2; o.w = y3;
            ((float4*)(outf + (size_t)row * out_stride))[j * 32 + lane] = o;
        }
    }
}

// --------------- fused assemble (cls+patch+pos) + ln_pre -> x --------------
__global__ __launch_bounds__(256) void k_asmln(
    const float* __restrict__ pe, const float* __restrict__ cls,
    const float* __restrict__ pos,
    const float* __restrict__ sc, const float* __restrict__ bi,
    float* __restrict__ x)
{
    int t = blockIdx.x * 8 + (threadIdx.x >> 5);
    if (t >= NTOK) return;
    int lane = threadIdx.x & 31;
    int s_ = t % Ss, b = t / Ss;
    const float4* src4 = (s_ == 0) ? (const float4*)cls
                       : (const float4*)(pe + (size_t)(b * NPATCH + s_ - 1) * Dm);
    const float4* pos4 = (const float4*)(pos + (size_t)s_ * Dm);
    float4 v[6];
    float s = 0.f, sq = 0.f;
    #pragma unroll
    for (int j = 0; j < 6; j++) {
        float4 a = src4[j * 32 + lane], p = pos4[j * 32 + lane];
        v[j].x = a.x + p.x; v[j].y = a.y + p.y; v[j].z = a.z + p.z; v[j].w = a.w + p.w;
        s  += v[j].x + v[j].y + v[j].z + v[j].w;
        sq += v[j].x*v[j].x + v[j].y*v[j].y + v[j].z*v[j].z + v[j].w*v[j].w;
    }
    #pragma unroll
    for (int o = 16; o > 0; o >>= 1) {
        s  += __shfl_xor_sync(~0u, s, o);
        sq += __shfl_xor_sync(~0u, sq, o);
    }
    float mean = s * (1.f / Dm);
    float var  = sq * (1.f / Dm) - mean * mean;
    float r = rsqrtf(var + 1e-5f);
    const float4* sc4 = (const float4*)sc;
    const float4* bi4 = (const float4*)bi;
    #pragma unroll
    for (int j = 0; j < 6; j++) {
        float4 g = sc4[j * 32 + lane], be = bi4[j * 32 + lane];
        float4 o;
        o.x = (v[j].x - mean) * r * g.x + be.x;
        o.y = (v[j].y - mean) * r * g.y + be.y;
        o.z = (v[j].z - mean) * r * g.z + be.z;
        o.w = (v[j].w - mean) * r * g.w + be.w;
        ((float4*)(x + (size_t)t * Dm))[j * 32 + lane] = o;
    }
}

// ------------------------- head: cls_ln @ vis_proj -------------------------
__global__ __launch_bounds__(512) void k_head(const float* __restrict__ cls,
                                              const float* __restrict__ Wp,
                                              float* __restrict__ out)
{
    __shared__ float row[Dm];
    int b = blockIdx.x;
    for (int i = threadIdx.x; i < Dm; i += 512) row[i] = cls[(size_t)b * Dm + i];
    __syncthreads();
    int o = threadIdx.x;
    float acc = 0.f;
    for (int d = 0; d < Dm; d++) acc += row[d] * Wp[(size_t)d * Oo + o];
    out[(size_t)b * Oo + o] = acc;
}

// ---------------------------------------------------------------------------
extern "C" void kernel_launch(void* const* d_in, const int* in_sizes, int n_in,
                              void* d_out, int out_size)
{
    const float* images   = (const float*)d_in[0];
    const float* conv_w   = (const float*)d_in[1];
    const float* cls_emb  = (const float*)d_in[2];
    const float* pos_emb  = (const float*)d_in[3];
    const float* ln_pre_s = (const float*)d_in[4];
    const float* ln_pre_b = (const float*)d_in[5];
    const float* ln1_s    = (const float*)d_in[6];
    const float* ln1_b    = (const float*)d_in[7];
    const float* qkv_w    = (const float*)d_in[8];
    const float* qkv_b    = (const float*)d_in[9];
    const float* out_w    = (const float*)d_in[10];
    const float* out_b    = (const float*)d_in[11];
    const float* ln2_s    = (const float*)d_in[12];
    const float* ln2_b    = (const float*)d_in[13];
    const float* fc_w     = (const float*)d_in[14];
    const float* fc_b     = (const float*)d_in[15];
    const float* proj_w   = (const float*)d_in[16];
    const float* proj_b   = (const float*)d_in[17];
    const float* lnp_s    = (const float*)d_in[18];
    const float* lnp_b    = (const float*)d_in[19];
    const float* vis_proj = (const float*)d_in[20];
    float* outp = (float*)d_out;

    __half *w, *xp, *h, *qkvh, *ao, *mlp;
    float *pe, *x, *cls;
    cudaGetSymbolAddress((void**)&w,    g_w);
    cudaGetSymbolAddress((void**)&xp,   g_xp);
    cudaGetSymbolAddress((void**)&pe,   g_pe);
    cudaGetSymbolAddress((void**)&x,    g_x);
    cudaGetSymbolAddress((void**)&h,    g_h);
    cudaGetSymbolAddress((void**)&qkvh, g_qkvh);
    cudaGetSymbolAddress((void**)&ao,   g_ao);
    cudaGetSymbolAddress((void**)&mlp,  g_mlp);
    cudaGetSymbolAddress((void**)&cls,  g_cls);

    cudaFuncSetAttribute(k_mm<false,false,false,false>, cudaFuncAttributeMaxDynamicSharedMemorySize, MM_SMEM);
    cudaFuncSetAttribute(k_mm<true, false,false,true >, cudaFuncAttributeMaxDynamicSharedMemorySize, MM_SMEM);
    cudaFuncSetAttribute(k_mm<true, true, false,false>, cudaFuncAttributeMaxDynamicSharedMemorySize, MM_SMEM);
    cudaFuncSetAttribute(k_mm<true, false,true, true >, cudaFuncAttributeMaxDynamicSharedMemorySize, MM_SMEM);
    cudaFuncSetAttribute(k_attn, cudaFuncAttributeMaxDynamicSharedMemorySize, ATT_SMEM);

    // ---- all weights fp32 -> fp16, one launch ----
    k_cvt_all<<<(F4_TOT + 255) / 256, 256>>>(
        (const float4*)conv_w, (const float4*)qkv_w, (const float4*)out_w,
        (const float4*)fc_w, (const float4*)proj_w, (__half2*)w);

    // ---- stem ----
    k_patchify<<<(NPROW * Dm + 255) / 256, 256>>>(images, xp);
    k_mm<false,false,false,false><<<dim3(Dm / 128, (NPROW + 127) / 128), 256, MM_SMEM>>>(
        xp, w + OFF_CONV, nullptr, nullptr, pe, nullptr, NPROW, Dm, Dm);
    k_asmln<<<(NTOK + 7) / 8, 256>>>(pe, cls_emb, pos_emb, ln_pre_s, ln_pre_b, x);

    // ---- transformer layers ----
    for (int l = 0; l < Ll; l++) {
        const float* l1s = ln1_s + (size_t)l * Dm;
        const float* l1b = ln1_b + (size_t)l * Dm;
        const float* qb  = qkv_b + (size_t)l * 3 * Dm;
        const float* ob  = out_b + (size_t)l * Dm;
        const float* l2s = ln2_s + (size_t)l * Dm;
        const float* l2b = ln2_b + (size_t)l * Dm;
        const float* fb  = fc_b  + (size_t)l * Ff;
        const float* pb  = proj_b + (size_t)l * Dm;
        const __half* qw = w + OFF_QKV  + (size_t)l * 2304 * 768;
        const __half* ow = w + OFF_OUT  + (size_t)l * 768 * 768;
        const __half* fw = w + OFF_FC   + (size_t)l * 3072 * 768;
        const __half* pw = w + OFF_PROJ + (size_t)l * 768 * 3072;

        k_ln<true><<<(NTOK + 7) / 8, 256>>>(x, nullptr, h, l1s, l1b, Dm, Dm, NTOK);
        k_mm<true,false,false,true><<<dim3(3 * Dm / 128, (NTOK + 127) / 128), 256, MM_SMEM>>>(
            h, qw, qb, nullptr, nullptr, qkvh, NTOK, 3 * Dm, Dm);
        k_attn<<<Bsz * Hh, ATT_THR, ATT_SMEM>>>(qkvh, ao);
        k_mm<true,true,false,false><<<dim3(Dm / 128, (NTOK + 127) / 128), 256, MM_SMEM>>>(
            ao, ow, ob, x, x, nullptr, NTOK, Dm, Dm);
        k_ln<true><<<(NTOK + 7) / 8, 256>>>(x, nullptr, h, l2s, l2b, Dm, Dm, NTOK);
        k_mm<true,false,true,true><<<dim3(Ff / 128, (NTOK + 127) / 128), 256, MM_SMEM>>>(
            h, fw, fb, nullptr, nullptr, mlp, NTOK, Ff, Dm);
        k_mm<true,true,false,false><<<dim3(Dm / 128, (NTOK + 127) / 128), 256, MM_SMEM>>>(
            mlp, pw, pb, x, x, nullptr, NTOK, Dm, Ff);
    }

    // ---- head ----
    k_ln<false><<<4, 256>>>(x, cls, nullptr, lnp_s, lnp_b, (long)Ss * Dm, Dm, Bsz);
    k_head<<<Bsz, 512>>>(cls, vis_proj, outp);
}